// round 8
// baseline (speedup 1.0000x reference)
#include <cuda_runtime.h>
#include <cuda_bf16.h>

#define N_NODES 50000
#define EDGES   800000
#define NODE_NF 128
#define EDGE_NF 64
#define IN_NF   192
#define H_NF    256
#define OUT_NF  128

#define NB 64              // nodes per MLP block
#define XS_STRIDE 193      // IN_NF + 1 (bank-conflict pad)
#define HS_STRIDE 257      // H_NF + 1

// Scratch for the segment-sum result (alloc-free rule: __device__ global).
__device__ float g_agg[(size_t)N_NODES * EDGE_NF];

// ---------------------------------------------------------------------------
// Zero the aggregate buffer (deterministic, graph-capturable).
// ---------------------------------------------------------------------------
__global__ void zero_agg_kernel() {
    int i = blockIdx.x * blockDim.x + threadIdx.x;
    if (i < (N_NODES * EDGE_NF) / 4) {
        reinterpret_cast<float4*>(g_agg)[i] = make_float4(0.f, 0.f, 0.f, 0.f);
    }
}

// ---------------------------------------------------------------------------
// Scatter-add edge_attr rows into g_agg by row index.
// edge_index is INT32 (JAX int64 downcasts to int32 without x64 mode; the
// harness metadata integer type is int32). One thread per (edge, float4
// chunk): vectorized read + 4 REDG.ADD to spread addresses.
// ---------------------------------------------------------------------------
__global__ void scatter_kernel(const int* __restrict__ edge_index,
                               const float* __restrict__ edge_attr) {
    int idx = blockIdx.x * blockDim.x + threadIdx.x;
    if (idx >= EDGES * (EDGE_NF / 4)) return;
    int e = idx >> 4;               // edge id
    int c = (idx & 15) << 2;        // channel base (0,4,...,60)
    int row = edge_index[e];        // edge_index[0][e] (first E int32s)
    if ((unsigned)row >= (unsigned)N_NODES) return;  // safety predicate
    float4 v = *reinterpret_cast<const float4*>(edge_attr + (size_t)e * EDGE_NF + c);
    float* dst = g_agg + (size_t)row * EDGE_NF + c;
    atomicAdd(dst + 0, v.x);
    atomicAdd(dst + 1, v.y);
    atomicAdd(dst + 2, v.z);
    atomicAdd(dst + 3, v.w);
}

// ---------------------------------------------------------------------------
// Fused 2-layer MLP: out = relu([nf | agg] @ W1 + b1) @ W2 + b2
// Block: 64 nodes, 256 threads. Thread (ng = t/32, cg = t%32):
//   GEMM1 microtile: nodes [ng*8, ng*8+8) x hidden cols [cg*8, cg*8+8)
//   GEMM2 microtile: nodes [ng*8, ng*8+8) x out cols    [cg*4, cg*4+4)
// Xs / Hs staged in padded dynamic smem; x-values warp-broadcast from LDS,
// weight rows read via __ldg (hot in L1/L2; total weights 320 KB).
// ---------------------------------------------------------------------------
__global__ __launch_bounds__(256, 1)
void mlp_kernel(const float* __restrict__ node_feats,
                const float* __restrict__ W1,
                const float* __restrict__ b1,
                const float* __restrict__ W2,
                const float* __restrict__ b2,
                float* __restrict__ out) {
    extern __shared__ float sm[];
    float* Xs = sm;                       // [NB][XS_STRIDE]
    float* Hs = sm + NB * XS_STRIDE;      // [NB][HS_STRIDE]

    const int node0 = blockIdx.x * NB;
    const int t = threadIdx.x;

    // ---- Stage X tile: node_feats part ----
    for (int i = t; i < NB * (NODE_NF / 4); i += 256) {
        int n = i >> 5;                 // / 32
        int c = (i & 31) << 2;
        int node = node0 + n;
        float4 v = (node < N_NODES)
            ? __ldg(reinterpret_cast<const float4*>(node_feats + (size_t)node * NODE_NF + c))
            : make_float4(0.f, 0.f, 0.f, 0.f);
        float* xp = Xs + n * XS_STRIDE + c;
        xp[0] = v.x; xp[1] = v.y; xp[2] = v.z; xp[3] = v.w;
    }
    // ---- Stage X tile: aggregate part ----
    for (int i = t; i < NB * (EDGE_NF / 4); i += 256) {
        int n = i >> 4;                 // / 16
        int c = (i & 15) << 2;
        int node = node0 + n;
        float4 v = (node < N_NODES)
            ? *reinterpret_cast<const float4*>(g_agg + (size_t)node * EDGE_NF + c)
            : make_float4(0.f, 0.f, 0.f, 0.f);
        float* xp = Xs + n * XS_STRIDE + NODE_NF + c;
        xp[0] = v.x; xp[1] = v.y; xp[2] = v.z; xp[3] = v.w;
    }
    __syncthreads();

    const int ng = t >> 5;        // node group 0..7
    const int cg = t & 31;        // column group 0..31
    const int nb0 = ng * 8;

    // ================= GEMM1: H = relu(X @ W1 + b1) =================
    {
        const int col0 = cg * 8;
        float acc[8][8];
        float bv[8];
        #pragma unroll
        for (int j = 0; j < 8; j++) bv[j] = __ldg(b1 + col0 + j);
        #pragma unroll
        for (int i = 0; i < 8; i++)
            #pragma unroll
            for (int j = 0; j < 8; j++) acc[i][j] = bv[j];

        #pragma unroll 2
        for (int k = 0; k < IN_NF; k++) {
            float4 wa = __ldg(reinterpret_cast<const float4*>(W1 + (size_t)k * H_NF + col0));
            float4 wb = __ldg(reinterpret_cast<const float4*>(W1 + (size_t)k * H_NF + col0 + 4));
            float w[8] = {wa.x, wa.y, wa.z, wa.w, wb.x, wb.y, wb.z, wb.w};
            #pragma unroll
            for (int i = 0; i < 8; i++) {
                float xv = Xs[(nb0 + i) * XS_STRIDE + k];   // warp-broadcast
                #pragma unroll
                for (int j = 0; j < 8; j++)
                    acc[i][j] = fmaf(xv, w[j], acc[i][j]);
            }
        }
        #pragma unroll
        for (int i = 0; i < 8; i++)
            #pragma unroll
            for (int j = 0; j < 8; j++)
                Hs[(nb0 + i) * HS_STRIDE + col0 + j] = fmaxf(acc[i][j], 0.f);
    }
    __syncthreads();

    // ================= GEMM2: out = H @ W2 + b2 =================
    {
        const int col0 = cg * 4;
        float acc[8][4];
        float bv[4];
        #pragma unroll
        for (int j = 0; j < 4; j++) bv[j] = __ldg(b2 + col0 + j);
        #pragma unroll
        for (int i = 0; i < 8; i++)
            #pragma unroll
            for (int j = 0; j < 4; j++) acc[i][j] = bv[j];

        #pragma unroll 4
        for (int k = 0; k < H_NF; k++) {
            float4 wv = __ldg(reinterpret_cast<const float4*>(W2 + (size_t)k * OUT_NF + col0));
            float w[4] = {wv.x, wv.y, wv.z, wv.w};
            #pragma unroll
            for (int i = 0; i < 8; i++) {
                float hv = Hs[(nb0 + i) * HS_STRIDE + k];   // warp-broadcast
                #pragma unroll
                for (int j = 0; j < 4; j++)
                    acc[i][j] = fmaf(hv, w[j], acc[i][j]);
            }
        }
        #pragma unroll
        for (int i = 0; i < 8; i++) {
            int node = node0 + nb0 + i;
            if (node < N_NODES) {
                float4 o = make_float4(acc[i][0], acc[i][1], acc[i][2], acc[i][3]);
                *reinterpret_cast<float4*>(out + (size_t)node * OUT_NF + col0) = o;
            }
        }
    }
}

// ---------------------------------------------------------------------------
// kernel_launch: inputs per metadata order:
//   0: node_feats [N, 128] f32
//   1: edge_index [2, E]   i32   (JAX int64 -> int32 without x64 mode)
//   2: edge_attr  [E, 64]  f32
//   3: W1 [192, 256] f32    4: b1 [256] f32
//   5: W2 [256, 128] f32    6: b2 [128] f32
// ---------------------------------------------------------------------------
extern "C" void kernel_launch(void* const* d_in, const int* in_sizes, int n_in,
                              void* d_out, int out_size) {
    const float* node_feats = (const float*)d_in[0];
    const int*   edge_index = (const int*)d_in[1];
    const float* edge_attr  = (const float*)d_in[2];
    const float* W1         = (const float*)d_in[3];
    const float* b1         = (const float*)d_in[4];
    const float* W2         = (const float*)d_in[5];
    const float* b2         = (const float*)d_in[6];
    float*       out        = (float*)d_out;

    // 1) zero aggregates
    {
        int total = (N_NODES * EDGE_NF) / 4;
        zero_agg_kernel<<<(total + 255) / 256, 256>>>();
    }
    // 2) scatter-add edges
    {
        int total = EDGES * (EDGE_NF / 4);
        scatter_kernel<<<(total + 255) / 256, 256>>>(edge_index, edge_attr);
    }
    // 3) fused MLP (unconditional attribute set: idempotent, not a stream op,
    //    no static guards)
    {
        const int smem = (NB * XS_STRIDE + NB * HS_STRIDE) * sizeof(float); // 115200 B
        cudaFuncSetAttribute(mlp_kernel,
                             cudaFuncAttributeMaxDynamicSharedMemorySize, smem);
        int blocks = (N_NODES + NB - 1) / NB;   // 782
        mlp_kernel<<<blocks, 256, smem>>>(node_feats, W1, b1, W2, b2, out);
    }
}

// round 11
// speedup vs baseline: 1.6260x; 1.6260x over previous
#include <cuda_runtime.h>
#include <cstdint>

#define N_NODES 50000
#define EDGES   800000
#define NODE_NF 128
#define EDGE_NF 64
#define IN_NF   192
#define H_NF    256
#define OUT_NF  128

#define XS_STRIDE 196   // tf32 words per X row (192 + 4 pad) -> conflict-free frags
#define HS_STRIDE 260   // tf32 words per H row (256 + 4 pad)
#define SMEM_TOTAL (128 * HS_STRIDE * 4)   // 133120 B (Hs union >= Xs union)

// Scratch for the segment-sum result (alloc-free rule: __device__ global).
__device__ float g_agg[(size_t)N_NODES * EDGE_NF];

// ---------------------------------------------------------------------------
__global__ void zero_agg_kernel() {
    int i = blockIdx.x * blockDim.x + threadIdx.x;
    if (i < (N_NODES * EDGE_NF) / 4)
        reinterpret_cast<float4*>(g_agg)[i] = make_float4(0.f, 0.f, 0.f, 0.f);
}

__global__ void scatter_kernel(const int* __restrict__ edge_index,
                               const float* __restrict__ edge_attr) {
    int idx = blockIdx.x * blockDim.x + threadIdx.x;
    if (idx >= EDGES * (EDGE_NF / 4)) return;
    int e = idx >> 4;
    int c = (idx & 15) << 2;
    int row = edge_index[e];
    if ((unsigned)row >= (unsigned)N_NODES) return;
    float4 v = *reinterpret_cast<const float4*>(edge_attr + (size_t)e * EDGE_NF + c);
    float* dst = g_agg + (size_t)row * EDGE_NF + c;
    atomicAdd(dst + 0, v.x);
    atomicAdd(dst + 1, v.y);
    atomicAdd(dst + 2, v.z);
    atomicAdd(dst + 3, v.w);
}

// ---------------------------------------------------------------------------
// mma.sync helpers (base-arch HMMA path; tcgen05 is sm_103a-gated and the
// harness compiles to plain sm_103 PTX target).
// ---------------------------------------------------------------------------
__device__ __forceinline__ uint32_t f2tf(float f) {
    uint32_t u;
    asm("cvt.rna.tf32.f32 %0, %1;" : "=r"(u) : "f"(f));
    return u;
}

__device__ __forceinline__ void mma8(float* c, const uint32_t* a, const uint32_t* b) {
    asm volatile(
        "mma.sync.aligned.m16n8k8.row.col.f32.tf32.tf32.f32 "
        "{%0,%1,%2,%3}, {%4,%5,%6,%7}, {%8,%9}, {%0,%1,%2,%3};"
        : "+f"(c[0]), "+f"(c[1]), "+f"(c[2]), "+f"(c[3])
        : "r"(a[0]), "r"(a[1]), "r"(a[2]), "r"(a[3]), "r"(b[0]), "r"(b[1]));
}

// ---------------------------------------------------------------------------
// Fused MLP via tf32 mma.sync. 512 threads (16 warps, 4x4 warp grid),
// 128 nodes per CTA.
//   GEMM1: warp tile 32(M) x 64(N), K=192  (acc 2x8x4)
//   GEMM2: warp tile 32(M) x 32(N), K=256  (acc 2x4x4)
// X staged in smem as tf32 (stride 196); H = relu(XW1+b1) written back into
// the same smem union as tf32 (stride 260). B fragments __ldg'd from gmem
// (weights L2-resident; frag pattern is sector-exact).
// ---------------------------------------------------------------------------
__global__ __launch_bounds__(512, 1)
void mlp_mma_kernel(const float* __restrict__ node_feats,
                    const float* __restrict__ W1,
                    const float* __restrict__ b1,
                    const float* __restrict__ W2,
                    const float* __restrict__ b2,
                    float* __restrict__ out) {
    extern __shared__ uint32_t sm_u[];
    const int tid = threadIdx.x;
    const int node0 = blockIdx.x * 128;

    // ---- Stage X (node_feats | agg) -> smem, rounded to tf32 ----
    for (int i = tid; i < 128 * 48; i += 512) {
        int row = i / 48;
        int q = i % 48;                  // float4 index within 192-wide row
        int node = node0 + row;
        float4 v = make_float4(0.f, 0.f, 0.f, 0.f);
        if (node < N_NODES) {
            v = (q < 32)
                ? __ldg(reinterpret_cast<const float4*>(node_feats + (size_t)node * NODE_NF) + q)
                : __ldg(reinterpret_cast<const float4*>(g_agg + (size_t)node * EDGE_NF) + (q - 32));
        }
        uint32_t* dst = sm_u + row * XS_STRIDE + q * 4;
        dst[0] = f2tf(v.x); dst[1] = f2tf(v.y);
        dst[2] = f2tf(v.z); dst[3] = f2tf(v.w);
    }
    __syncthreads();

    const int w = tid >> 5, lane = tid & 31;
    const int g = lane >> 2, tg = lane & 3;
    const int wm = (w & 3) * 32;         // M block (shared by both GEMMs)
    const int wn1 = (w >> 2) * 64;       // GEMM1 N block
    const int wn2 = (w >> 2) * 32;       // GEMM2 N block

    // ================= GEMM1: acc = X @ W1 =================
    float acc[2][8][4];
    #pragma unroll
    for (int i = 0; i < 2; i++)
        #pragma unroll
        for (int j = 0; j < 8; j++)
            #pragma unroll
            for (int c = 0; c < 4; c++) acc[i][j][c] = 0.f;

    #pragma unroll 2
    for (int ks = 0; ks < IN_NF / 8; ks++) {
        const int k0 = ks * 8;
        uint32_t af[2][4];
        #pragma unroll
        for (int i = 0; i < 2; i++) {
            const uint32_t* xr = sm_u + (wm + i * 16 + g) * XS_STRIDE + k0 + tg;
            af[i][0] = xr[0];
            af[i][2] = xr[4];
            af[i][1] = xr[8 * XS_STRIDE];
            af[i][3] = xr[8 * XS_STRIDE + 4];
        }
        uint32_t bf[8][2];
        const float* wp = W1 + (size_t)(k0 + tg) * H_NF + wn1 + g;
        #pragma unroll
        for (int j = 0; j < 8; j++) {
            bf[j][0] = f2tf(__ldg(wp + j * 8));
            bf[j][1] = f2tf(__ldg(wp + 4 * H_NF + j * 8));
        }
        #pragma unroll
        for (int i = 0; i < 2; i++)
            #pragma unroll
            for (int j = 0; j < 8; j++)
                mma8(acc[i][j], af[i], bf[j]);
    }
    __syncthreads();   // all Xs reads done before Hs overwrites the union

    // ---- Epilogue 1: bias + relu -> Hs (tf32) ----
    #pragma unroll
    for (int i = 0; i < 2; i++) {
        const int row = wm + i * 16 + g;
        #pragma unroll
        for (int j = 0; j < 8; j++) {
            const int col = wn1 + j * 8 + 2 * tg;
            float bb0 = __ldg(b1 + col), bb1 = __ldg(b1 + col + 1);
            sm_u[row * HS_STRIDE + col]           = f2tf(fmaxf(acc[i][j][0] + bb0, 0.f));
            sm_u[row * HS_STRIDE + col + 1]       = f2tf(fmaxf(acc[i][j][1] + bb1, 0.f));
            sm_u[(row + 8) * HS_STRIDE + col]     = f2tf(fmaxf(acc[i][j][2] + bb0, 0.f));
            sm_u[(row + 8) * HS_STRIDE + col + 1] = f2tf(fmaxf(acc[i][j][3] + bb1, 0.f));
        }
    }
    __syncthreads();

    // ================= GEMM2: acc2 = relu(H) @ W2 =================
    float acc2[2][4][4];
    #pragma unroll
    for (int i = 0; i < 2; i++)
        #pragma unroll
        for (int j = 0; j < 4; j++)
            #pragma unroll
            for (int c = 0; c < 4; c++) acc2[i][j][c] = 0.f;

    #pragma unroll 2
    for (int ks = 0; ks < H_NF / 8; ks++) {
        const int k0 = ks * 8;
        uint32_t af[2][4];
        #pragma unroll
        for (int i = 0; i < 2; i++) {
            const uint32_t* hr = sm_u + (wm + i * 16 + g) * HS_STRIDE + k0 + tg;
            af[i][0] = hr[0];
            af[i][2] = hr[4];
            af[i][1] = hr[8 * HS_STRIDE];
            af[i][3] = hr[8 * HS_STRIDE + 4];
        }
        uint32_t bf[4][2];
        const float* wp = W2 + (size_t)(k0 + tg) * OUT_NF + wn2 + g;
        #pragma unroll
        for (int j = 0; j < 4; j++) {
            bf[j][0] = f2tf(__ldg(wp + j * 8));
            bf[j][1] = f2tf(__ldg(wp + 4 * OUT_NF + j * 8));
        }
        #pragma unroll
        for (int i = 0; i < 2; i++)
            #pragma unroll
            for (int j = 0; j < 4; j++)
                mma8(acc2[i][j], af[i], bf[j]);
    }

    // ---- Epilogue 2: bias -> gmem ----
    #pragma unroll
    for (int i = 0; i < 2; i++) {
        const int row = wm + i * 16 + g;
        const int nodeA = node0 + row;
        const int nodeB = nodeA + 8;
        #pragma unroll
        for (int j = 0; j < 4; j++) {
            const int col = wn2 + j * 8 + 2 * tg;
            float bb0 = __ldg(b2 + col), bb1 = __ldg(b2 + col + 1);
            if (nodeA < N_NODES) {
                out[(size_t)nodeA * OUT_NF + col]     = acc2[i][j][0] + bb0;
                out[(size_t)nodeA * OUT_NF + col + 1] = acc2[i][j][1] + bb1;
            }
            if (nodeB < N_NODES) {
                out[(size_t)nodeB * OUT_NF + col]     = acc2[i][j][2] + bb0;
                out[(size_t)nodeB * OUT_NF + col + 1] = acc2[i][j][3] + bb1;
            }
        }
    }
}

// ---------------------------------------------------------------------------
extern "C" void kernel_launch(void* const* d_in, const int* in_sizes, int n_in,
                              void* d_out, int out_size) {
    const float* node_feats = (const float*)d_in[0];
    const int*   edge_index = (const int*)d_in[1];
    const float* edge_attr  = (const float*)d_in[2];
    const float* W1         = (const float*)d_in[3];
    const float* b1         = (const float*)d_in[4];
    const float* W2         = (const float*)d_in[5];
    const float* b2         = (const float*)d_in[6];
    float*       out        = (float*)d_out;

    {
        int total = (N_NODES * EDGE_NF) / 4;
        zero_agg_kernel<<<(total + 255) / 256, 256>>>();
    }
    {
        int total = EDGES * (EDGE_NF / 4);
        scatter_kernel<<<(total + 255) / 256, 256>>>(edge_index, edge_attr);
    }
    {
        cudaFuncSetAttribute(mlp_mma_kernel,
                             cudaFuncAttributeMaxDynamicSharedMemorySize, SMEM_TOTAL);
        int blocks = (N_NODES + 127) / 128;   // 391
        mlp_mma_kernel<<<blocks, 512, SMEM_TOTAL>>>(node_feats, W1, b1, W2, b2, out);
    }
}

// round 12
// speedup vs baseline: 1.6820x; 1.0344x over previous
#include <cuda_runtime.h>
#include <cstdint>

#define N_NODES 50000
#define EDGES   800000
#define NODE_NF 128
#define EDGE_NF 64
#define IN_NF   192
#define H_NF    256
#define OUT_NF  128

#define XS_STRIDE 196   // tf32 words per X row (192 + 4 pad) -> conflict-free frags
#define HS_STRIDE 260   // tf32 words per H row (256 + 4 pad)
#define SMEM_TOTAL (128 * HS_STRIDE * 4)   // 133120 B

// Device scratch (alloc-free rule: __device__ globals).
__device__ float    g_agg[(size_t)N_NODES * EDGE_NF];
__device__ uint32_t g_W1p[IN_NF * H_NF];    // frag-packed tf32 W1
__device__ uint32_t g_W2p[H_NF * OUT_NF];   // frag-packed tf32 W2

__device__ __forceinline__ uint32_t f2tf(float f) {
    uint32_t u;
    asm("cvt.rna.tf32.f32 %0, %1;" : "=r"(u) : "f"(f));
    return u;
}

__device__ __forceinline__ void mma8(float* c, const uint32_t* a, const uint32_t* b) {
    asm volatile(
        "mma.sync.aligned.m16n8k8.row.col.f32.tf32.tf32.f32 "
        "{%0,%1,%2,%3}, {%4,%5,%6,%7}, {%8,%9}, {%0,%1,%2,%3};"
        : "+f"(c[0]), "+f"(c[1]), "+f"(c[2]), "+f"(c[3])
        : "r"(a[0]), "r"(a[1]), "r"(a[2]), "r"(a[3]), "r"(b[0]), "r"(b[1]));
}

// ---------------------------------------------------------------------------
// Weight pack kernels: canonical [K][N] f32 -> frag-ordered tf32 so each lane
// reads contiguous 64B (GEMM1) / 32B (GEMM2) per k-step.
// GEMM1 layout: g_W1p[(((ks*4+nb)*32+l)*16) + j*2+h]
//             = tf32(W1[(ks*8 + tg + h*4) * H_NF + nb*64 + g + j*8])
//   where g=l>>2, tg=l&3, ks in [0,24), nb in [0,4), j in [0,8), h in {0,1}
// ---------------------------------------------------------------------------
__global__ void pack_w1_kernel(const float* __restrict__ W1) {
    int i = blockIdx.x * blockDim.x + threadIdx.x;
    if (i >= IN_NF * H_NF) return;
    int idx = i & 15, l = (i >> 4) & 31, blk = i >> 9;   // blk = ks*4+nb
    int ks = blk >> 2, nb = blk & 3;
    int g = l >> 2, tg = l & 3, j = idx >> 1, h = idx & 1;
    int k = ks * 8 + tg + h * 4;
    int col = nb * 64 + g + j * 8;
    g_W1p[i] = f2tf(__ldg(W1 + (size_t)k * H_NF + col));
}

// GEMM2 layout: g_W2p[(((ks*4+nb)*32+l)*8) + j*2+h]
//             = tf32(W2[(ks*8 + tg + h*4) * OUT_NF + nb*32 + g + j*8])
//   ks in [0,32), nb in [0,4), j in [0,4), h in {0,1}
__global__ void pack_w2_kernel(const float* __restrict__ W2) {
    int i = blockIdx.x * blockDim.x + threadIdx.x;
    if (i >= H_NF * OUT_NF) return;
    int idx = i & 7, l = (i >> 3) & 31, blk = i >> 8;
    int ks = blk >> 2, nb = blk & 3;
    int g = l >> 2, tg = l & 3, j = idx >> 1, h = idx & 1;
    int k = ks * 8 + tg + h * 4;
    int col = nb * 32 + g + j * 8;
    g_W2p[i] = f2tf(__ldg(W2 + (size_t)k * OUT_NF + col));
}

// ---------------------------------------------------------------------------
__global__ void scatter_kernel(const int* __restrict__ edge_index,
                               const float* __restrict__ edge_attr) {
    int idx = blockIdx.x * blockDim.x + threadIdx.x;
    if (idx >= EDGES * (EDGE_NF / 4)) return;
    int e = idx >> 4;
    int c = (idx & 15) << 2;
    int row = edge_index[e];
    if ((unsigned)row >= (unsigned)N_NODES) return;
    float4 v = *reinterpret_cast<const float4*>(edge_attr + (size_t)e * EDGE_NF + c);
    float* dst = g_agg + (size_t)row * EDGE_NF + c;
    atomicAdd(dst + 0, v.x);
    atomicAdd(dst + 1, v.y);
    atomicAdd(dst + 2, v.z);
    atomicAdd(dst + 3, v.w);
}

// ---------------------------------------------------------------------------
// Fused MLP via tf32 mma.sync. 512 threads (4x4 warp grid), 128 nodes/CTA.
// B fragments come from frag-packed tf32 buffers: 4 / 2 LDG.128 per k-step.
// ---------------------------------------------------------------------------
__global__ __launch_bounds__(512, 1)
void mlp_mma_kernel(const float* __restrict__ node_feats,
                    const float* __restrict__ b1,
                    const float* __restrict__ b2,
                    float* __restrict__ out) {
    extern __shared__ uint32_t sm_u[];
    const int tid = threadIdx.x;
    const int node0 = blockIdx.x * 128;

    // ---- Stage X (node_feats | agg) -> smem, rounded to tf32 ----
    for (int i = tid; i < 128 * 48; i += 512) {
        int row = i / 48;
        int q = i % 48;
        int node = node0 + row;
        float4 v = make_float4(0.f, 0.f, 0.f, 0.f);
        if (node < N_NODES) {
            v = (q < 32)
                ? __ldg(reinterpret_cast<const float4*>(node_feats + (size_t)node * NODE_NF) + q)
                : __ldg(reinterpret_cast<const float4*>(g_agg + (size_t)node * EDGE_NF) + (q - 32));
        }
        uint32_t* dst = sm_u + row * XS_STRIDE + q * 4;
        dst[0] = f2tf(v.x); dst[1] = f2tf(v.y);
        dst[2] = f2tf(v.z); dst[3] = f2tf(v.w);
    }
    __syncthreads();

    const int w = tid >> 5, lane = tid & 31;
    const int g = lane >> 2, tg = lane & 3;
    const int wm = (w & 3) * 32;         // M block
    const int nb = w >> 2;               // N block id (0..3)
    const int wn1 = nb * 64;             // GEMM1 N offset
    const int wn2 = nb * 32;             // GEMM2 N offset

    // ================= GEMM1: acc = X @ W1 =================
    float acc[2][8][4];
    #pragma unroll
    for (int i = 0; i < 2; i++)
        #pragma unroll
        for (int j = 0; j < 8; j++)
            #pragma unroll
            for (int c = 0; c < 4; c++) acc[i][j][c] = 0.f;

    #pragma unroll 2
    for (int ks = 0; ks < IN_NF / 8; ks++) {
        const int k0 = ks * 8;
        uint32_t af[2][4];
        #pragma unroll
        for (int i = 0; i < 2; i++) {
            const uint32_t* xr = sm_u + (wm + i * 16 + g) * XS_STRIDE + k0 + tg;
            af[i][0] = xr[0];
            af[i][2] = xr[4];
            af[i][1] = xr[8 * XS_STRIDE];
            af[i][3] = xr[8 * XS_STRIDE + 4];
        }
        // frag-packed B: 4 x LDG.128, contiguous 64B per lane
        const uint4* bp = reinterpret_cast<const uint4*>(g_W1p)
                        + ((((ks * 4 + nb) * 32) + lane) << 2);
        uint4 q0 = __ldg(bp + 0), q1 = __ldg(bp + 1);
        uint4 q2 = __ldg(bp + 2), q3 = __ldg(bp + 3);
        uint32_t bw[16] = {q0.x, q0.y, q0.z, q0.w, q1.x, q1.y, q1.z, q1.w,
                           q2.x, q2.y, q2.z, q2.w, q3.x, q3.y, q3.z, q3.w};
        #pragma unroll
        for (int i = 0; i < 2; i++)
            #pragma unroll
            for (int j = 0; j < 8; j++)
                mma8(acc[i][j], af[i], &bw[j * 2]);
    }
    __syncthreads();   // all Xs reads done before Hs overwrites the union

    // ---- Epilogue 1: bias + relu -> Hs (tf32) ----
    #pragma unroll
    for (int i = 0; i < 2; i++) {
        const int row = wm + i * 16 + g;
        #pragma unroll
        for (int j = 0; j < 8; j++) {
            const int col = wn1 + j * 8 + 2 * tg;
            float bb0 = __ldg(b1 + col), bb1 = __ldg(b1 + col + 1);
            sm_u[row * HS_STRIDE + col]           = f2tf(fmaxf(acc[i][j][0] + bb0, 0.f));
            sm_u[row * HS_STRIDE + col + 1]       = f2tf(fmaxf(acc[i][j][1] + bb1, 0.f));
            sm_u[(row + 8) * HS_STRIDE + col]     = f2tf(fmaxf(acc[i][j][2] + bb0, 0.f));
            sm_u[(row + 8) * HS_STRIDE + col + 1] = f2tf(fmaxf(acc[i][j][3] + bb1, 0.f));
        }
    }
    __syncthreads();

    // ================= GEMM2: acc2 = relu(H) @ W2 =================
    float acc2[2][4][4];
    #pragma unroll
    for (int i = 0; i < 2; i++)
        #pragma unroll
        for (int j = 0; j < 4; j++)
            #pragma unroll
            for (int c = 0; c < 4; c++) acc2[i][j][c] = 0.f;

    #pragma unroll 2
    for (int ks = 0; ks < H_NF / 8; ks++) {
        const int k0 = ks * 8;
        uint32_t af[2][4];
        #pragma unroll
        for (int i = 0; i < 2; i++) {
            const uint32_t* hr = sm_u + (wm + i * 16 + g) * HS_STRIDE + k0 + tg;
            af[i][0] = hr[0];
            af[i][2] = hr[4];
            af[i][1] = hr[8 * HS_STRIDE];
            af[i][3] = hr[8 * HS_STRIDE + 4];
        }
        const uint4* bp = reinterpret_cast<const uint4*>(g_W2p)
                        + ((((ks * 4 + nb) * 32) + lane) << 1);
        uint4 q0 = __ldg(bp + 0), q1 = __ldg(bp + 1);
        uint32_t bw[8] = {q0.x, q0.y, q0.z, q0.w, q1.x, q1.y, q1.z, q1.w};
        #pragma unroll
        for (int i = 0; i < 2; i++)
            #pragma unroll
            for (int j = 0; j < 4; j++)
                mma8(acc2[i][j], af[i], &bw[j * 2]);
    }

    // ---- Epilogue 2: bias -> gmem ----
    #pragma unroll
    for (int i = 0; i < 2; i++) {
        const int row = wm + i * 16 + g;
        const int nodeA = node0 + row;
        const int nodeB = nodeA + 8;
        #pragma unroll
        for (int j = 0; j < 4; j++) {
            const int col = wn2 + j * 8 + 2 * tg;
            float bb0 = __ldg(b2 + col), bb1 = __ldg(b2 + col + 1);
            if (nodeA < N_NODES) {
                out[(size_t)nodeA * OUT_NF + col]     = acc2[i][j][0] + bb0;
                out[(size_t)nodeA * OUT_NF + col + 1] = acc2[i][j][1] + bb1;
            }
            if (nodeB < N_NODES) {
                out[(size_t)nodeB * OUT_NF + col]     = acc2[i][j][2] + bb0;
                out[(size_t)nodeB * OUT_NF + col + 1] = acc2[i][j][3] + bb1;
            }
        }
    }
}

// ---------------------------------------------------------------------------
extern "C" void kernel_launch(void* const* d_in, const int* in_sizes, int n_in,
                              void* d_out, int out_size) {
    const float* node_feats = (const float*)d_in[0];
    const int*   edge_index = (const int*)d_in[1];
    const float* edge_attr  = (const float*)d_in[2];
    const float* W1         = (const float*)d_in[3];
    const float* b1         = (const float*)d_in[4];
    const float* W2         = (const float*)d_in[5];
    const float* b2         = (const float*)d_in[6];
    float*       out        = (float*)d_out;

    // 1) zero aggregates via async memset (graph-capturable, not a kernel launch)
    void* agg_ptr = nullptr;
    cudaGetSymbolAddress(&agg_ptr, g_agg);
    cudaMemsetAsync(agg_ptr, 0, (size_t)N_NODES * EDGE_NF * sizeof(float));

    // 2) pack weights to frag-ordered tf32 (independent of scatter)
    pack_w1_kernel<<<(IN_NF * H_NF + 255) / 256, 256>>>(W1);
    pack_w2_kernel<<<(H_NF * OUT_NF + 255) / 256, 256>>>(W2);

    // 3) scatter-add edges
    {
        int total = EDGES * (EDGE_NF / 4);
        scatter_kernel<<<(total + 255) / 256, 256>>>(edge_index, edge_attr);
    }

    // 4) fused MLP
    {
        cudaFuncSetAttribute(mlp_mma_kernel,
                             cudaFuncAttributeMaxDynamicSharedMemorySize, SMEM_TOTAL);
        int blocks = (N_NODES + 127) / 128;   // 391
        mlp_mma_kernel<<<blocks, 512, SMEM_TOTAL>>>(node_feats, b1, b2, out);
    }
}

// round 14
// speedup vs baseline: 2.2440x; 1.3341x over previous
#include <cuda_runtime.h>
#include <cstdint>

#define N_NODES 50000
#define EDGES   800000
#define NODE_NF 128
#define EDGE_NF 64
#define IN_NF   192
#define H_NF    256
#define OUT_NF  128

#define ROWS_CTA 64     // nodes per MLP CTA (256 threads, 2 CTAs/SM)
#define XS_STRIDE 196   // tf32 words per X row (192 + 4 pad)
#define HS_STRIDE 260   // tf32 words per H row (256 + 4 pad)
#define SMEM_TOTAL (ROWS_CTA * HS_STRIDE * 4)   // 66560 B

// Device scratch (alloc-free rule: __device__ globals).
__device__ float    g_agg[(size_t)N_NODES * EDGE_NF];
__device__ uint32_t g_W1p[IN_NF * H_NF];    // frag-packed tf32 W1
__device__ uint32_t g_W2p[H_NF * OUT_NF];   // frag-packed tf32 W2

__device__ __forceinline__ uint32_t f2tf(float f) {
    uint32_t u;
    asm("cvt.rna.tf32.f32 %0, %1;" : "=r"(u) : "f"(f));
    return u;
}

__device__ __forceinline__ void mma8(float* c, const uint32_t* a, const uint32_t* b) {
    asm volatile(
        "mma.sync.aligned.m16n8k8.row.col.f32.tf32.tf32.f32 "
        "{%0,%1,%2,%3}, {%4,%5,%6,%7}, {%8,%9}, {%0,%1,%2,%3};"
        : "+f"(c[0]), "+f"(c[1]), "+f"(c[2]), "+f"(c[3])
        : "r"(a[0]), "r"(a[1]), "r"(a[2]), "r"(a[3]), "r"(b[0]), "r"(b[1]));
}

// ---------------------------------------------------------------------------
// Weight pack kernels (canonical [K][N] f32 -> frag-ordered tf32).
// ---------------------------------------------------------------------------
__global__ void pack_w1_kernel(const float* __restrict__ W1) {
    int i = blockIdx.x * blockDim.x + threadIdx.x;
    if (i >= IN_NF * H_NF) return;
    int idx = i & 15, l = (i >> 4) & 31, blk = i >> 9;   // blk = ks*4+nb
    int ks = blk >> 2, nb = blk & 3;
    int g = l >> 2, tg = l & 3, j = idx >> 1, h = idx & 1;
    int k = ks * 8 + tg + h * 4;
    int col = nb * 64 + g + j * 8;
    g_W1p[i] = f2tf(__ldg(W1 + (size_t)k * H_NF + col));
}

__global__ void pack_w2_kernel(const float* __restrict__ W2) {
    int i = blockIdx.x * blockDim.x + threadIdx.x;
    if (i >= H_NF * OUT_NF) return;
    int idx = i & 7, l = (i >> 3) & 31, blk = i >> 8;
    int ks = blk >> 2, nb = blk & 3;
    int g = l >> 2, tg = l & 3, j = idx >> 1, h = idx & 1;
    int k = ks * 8 + tg + h * 4;
    int col = nb * 32 + g + j * 8;
    g_W2p[i] = f2tf(__ldg(W2 + (size_t)k * OUT_NF + col));
}

// ---------------------------------------------------------------------------
// Scatter-add with vector reduction: one red.global.add.v4.f32 per thread
// (4x fewer atomic messages than scalar atomicAdd).
// ---------------------------------------------------------------------------
__global__ void scatter_kernel(const int* __restrict__ edge_index,
                               const float* __restrict__ edge_attr) {
    int idx = blockIdx.x * blockDim.x + threadIdx.x;
    if (idx >= EDGES * (EDGE_NF / 4)) return;
    int e = idx >> 4;
    int c = (idx & 15) << 2;
    int row = __ldg(edge_index + e);
    if ((unsigned)row >= (unsigned)N_NODES) return;
    float4 v = *reinterpret_cast<const float4*>(edge_attr + (size_t)e * EDGE_NF + c);
    float* dst = g_agg + (size_t)row * EDGE_NF + c;
    asm volatile("red.global.add.v4.f32 [%0], {%1,%2,%3,%4};"
                 :: "l"(dst), "f"(v.x), "f"(v.y), "f"(v.z), "f"(v.w)
                 : "memory");
}

// ---------------------------------------------------------------------------
// Fused MLP via tf32 mma.sync. 256 threads (2 M-blocks x 4 N-blocks warps),
// 64 nodes/CTA, 2 CTAs per SM (cross-CTA latency hiding).
// ---------------------------------------------------------------------------
__global__ __launch_bounds__(256, 2)
void mlp_mma_kernel(const float* __restrict__ node_feats,
                    const float* __restrict__ b1,
                    const float* __restrict__ b2,
                    float* __restrict__ out) {
    extern __shared__ uint32_t sm_u[];
    const int tid = threadIdx.x;
    const int node0 = blockIdx.x * ROWS_CTA;

    // ---- Stage X (node_feats | agg) -> smem, rounded to tf32 ----
    for (int i = tid; i < ROWS_CTA * 48; i += 256) {
        int row = i / 48;
        int q = i % 48;
        int node = node0 + row;
        float4 v = make_float4(0.f, 0.f, 0.f, 0.f);
        if (node < N_NODES) {
            v = (q < 32)
                ? __ldg(reinterpret_cast<const float4*>(node_feats + (size_t)node * NODE_NF) + q)
                : __ldg(reinterpret_cast<const float4*>(g_agg + (size_t)node * EDGE_NF) + (q - 32));
        }
        uint32_t* dst = sm_u + row * XS_STRIDE + q * 4;
        dst[0] = f2tf(v.x); dst[1] = f2tf(v.y);
        dst[2] = f2tf(v.z); dst[3] = f2tf(v.w);
    }
    __syncthreads();

    const int w = tid >> 5, lane = tid & 31;
    const int g = lane >> 2, tg = lane & 3;
    const int wm = (w & 1) * 32;         // M block (0 or 32)
    const int nb = w >> 1;               // N block id (0..3)
    const int wn1 = nb * 64;             // GEMM1 N offset
    const int wn2 = nb * 32;             // GEMM2 N offset

    // ================= GEMM1: acc = X @ W1 =================
    float acc[2][8][4];
    #pragma unroll
    for (int i = 0; i < 2; i++)
        #pragma unroll
        for (int j = 0; j < 8; j++)
            #pragma unroll
            for (int c = 0; c < 4; c++) acc[i][j][c] = 0.f;

    #pragma unroll 2
    for (int ks = 0; ks < IN_NF / 8; ks++) {
        const int k0 = ks * 8;
        uint32_t af[2][4];
        #pragma unroll
        for (int i = 0; i < 2; i++) {
            const uint32_t* xr = sm_u + (wm + i * 16 + g) * XS_STRIDE + k0 + tg;
            af[i][0] = xr[0];
            af[i][2] = xr[4];
            af[i][1] = xr[8 * XS_STRIDE];
            af[i][3] = xr[8 * XS_STRIDE + 4];
        }
        const uint4* bp = reinterpret_cast<const uint4*>(g_W1p)
                        + ((((ks * 4 + nb) * 32) + lane) << 2);
        uint4 q0 = __ldg(bp + 0), q1 = __ldg(bp + 1);
        uint4 q2 = __ldg(bp + 2), q3 = __ldg(bp + 3);
        uint32_t bw[16] = {q0.x, q0.y, q0.z, q0.w, q1.x, q1.y, q1.z, q1.w,
                           q2.x, q2.y, q2.z, q2.w, q3.x, q3.y, q3.z, q3.w};
        #pragma unroll
        for (int i = 0; i < 2; i++)
            #pragma unroll
            for (int j = 0; j < 8; j++)
                mma8(acc[i][j], af[i], &bw[j * 2]);
    }
    __syncthreads();   // all Xs reads done before Hs overwrites the union

    // ---- Epilogue 1: bias + relu -> Hs (tf32) ----
    #pragma unroll
    for (int i = 0; i < 2; i++) {
        const int row = wm + i * 16 + g;
        #pragma unroll
        for (int j = 0; j < 8; j++) {
            const int col = wn1 + j * 8 + 2 * tg;
            float bb0 = __ldg(b1 + col), bb1 = __ldg(b1 + col + 1);
            sm_u[row * HS_STRIDE + col]           = f2tf(fmaxf(acc[i][j][0] + bb0, 0.f));
            sm_u[row * HS_STRIDE + col + 1]       = f2tf(fmaxf(acc[i][j][1] + bb1, 0.f));
            sm_u[(row + 8) * HS_STRIDE + col]     = f2tf(fmaxf(acc[i][j][2] + bb0, 0.f));
            sm_u[(row + 8) * HS_STRIDE + col + 1] = f2tf(fmaxf(acc[i][j][3] + bb1, 0.f));
        }
    }
    __syncthreads();

    // ================= GEMM2: acc2 = relu(H) @ W2 =================
    float acc2[2][4][4];
    #pragma unroll
    for (int i = 0; i < 2; i++)
        #pragma unroll
        for (int j = 0; j < 4; j++)
            #pragma unroll
            for (int c = 0; c < 4; c++) acc2[i][j][c] = 0.f;

    #pragma unroll 2
    for (int ks = 0; ks < H_NF / 8; ks++) {
        const int k0 = ks * 8;
        uint32_t af[2][4];
        #pragma unroll
        for (int i = 0; i < 2; i++) {
            const uint32_t* hr = sm_u + (wm + i * 16 + g) * HS_STRIDE + k0 + tg;
            af[i][0] = hr[0];
            af[i][2] = hr[4];
            af[i][1] = hr[8 * HS_STRIDE];
            af[i][3] = hr[8 * HS_STRIDE + 4];
        }
        const uint4* bp = reinterpret_cast<const uint4*>(g_W2p)
                        + ((((ks * 4 + nb) * 32) + lane) << 1);
        uint4 q0 = __ldg(bp + 0), q1 = __ldg(bp + 1);
        uint32_t bw[8] = {q0.x, q0.y, q0.z, q0.w, q1.x, q1.y, q1.z, q1.w};
        #pragma unroll
        for (int i = 0; i < 2; i++)
            #pragma unroll
            for (int j = 0; j < 4; j++)
                mma8(acc2[i][j], af[i], &bw[j * 2]);
    }

    // ---- Epilogue 2: bias -> gmem ----
    #pragma unroll
    for (int i = 0; i < 2; i++) {
        const int row = wm + i * 16 + g;
        const int nodeA = node0 + row;
        const int nodeB = nodeA + 8;
        #pragma unroll
        for (int j = 0; j < 4; j++) {
            const int col = wn2 + j * 8 + 2 * tg;
            float bb0 = __ldg(b2 + col), bb1 = __ldg(b2 + col + 1);
            if (nodeA < N_NODES) {
                out[(size_t)nodeA * OUT_NF + col]     = acc2[i][j][0] + bb0;
                out[(size_t)nodeA * OUT_NF + col + 1] = acc2[i][j][1] + bb1;
            }
            if (nodeB < N_NODES) {
                out[(size_t)nodeB * OUT_NF + col]     = acc2[i][j][2] + bb0;
                out[(size_t)nodeB * OUT_NF + col + 1] = acc2[i][j][3] + bb1;
            }
        }
    }
}

// ---------------------------------------------------------------------------
extern "C" void kernel_launch(void* const* d_in, const int* in_sizes, int n_in,
                              void* d_out, int out_size) {
    const float* node_feats = (const float*)d_in[0];
    const int*   edge_index = (const int*)d_in[1];
    const float* edge_attr  = (const float*)d_in[2];
    const float* W1         = (const float*)d_in[3];
    const float* b1         = (const float*)d_in[4];
    const float* W2         = (const float*)d_in[5];
    const float* b2         = (const float*)d_in[6];
    float*       out        = (float*)d_out;

    // 1) zero aggregates via async memset
    void* agg_ptr = nullptr;
    cudaGetSymbolAddress(&agg_ptr, g_agg);
    cudaMemsetAsync(agg_ptr, 0, (size_t)N_NODES * EDGE_NF * sizeof(float));

    // 2) pack weights to frag-ordered tf32
    pack_w1_kernel<<<(IN_NF * H_NF + 255) / 256, 256>>>(W1);
    pack_w2_kernel<<<(H_NF * OUT_NF + 255) / 256, 256>>>(W2);

    // 3) scatter-add edges (vector reductions)
    {
        int total = EDGES * (EDGE_NF / 4);
        scatter_kernel<<<(total + 255) / 256, 256>>>(edge_index, edge_attr);
    }

    // 4) fused MLP
    {
        cudaFuncSetAttribute(mlp_mma_kernel,
                             cudaFuncAttributeMaxDynamicSharedMemorySize, SMEM_TOTAL);
        int blocks = (N_NODES + ROWS_CTA - 1) / ROWS_CTA;   // 782
        mlp_mma_kernel<<<blocks, 256, SMEM_TOTAL>>>(node_feats, b1, b2, out);
    }
}